// round 8
// baseline (speedup 1.0000x reference)
#include <cuda_runtime.h>
#include <math.h>
#include <float.h>

// Fixed problem shape: img (16,3,512,512) f32, sbin=4 -> out (16,31,128,128) f32
#define BATCH 16
#define NCH   3
#define IH    512
#define IW    512
#define BH    128
#define BW    128

#define TS     16         // cells per tile side
#define WROWS  68         // pixel rows in window
#define WCOLS  68         // pixel cols in window
#define MP     68         // smem pitch (u32), multiple of 4 for LDS.128
#define NSTRIP 18         // 4-px strips per row (covers sc -2..69)

#define HIST_ELEMS (BATCH * 18 * BH * BW)
#define NORM_ELEMS (BATCH * BH * BW)

__device__ float g_hist[HIST_ELEMS];
__device__ float g_norm[NORM_ELEMS];

// ---------------------------------------------------------------------------
// Kernel 1: gradients + orientation + per-cell gather + norm.
// One block = 16x16 cells. mag|bo packed in one u32 (bo in 5 low mantissa bits).
// Orientation argmax: EXACT u64 packed max tree —
//   key = (|dot| bits [30:0]) << 6 | (positive ? 32 : 0) | (31 - k)
// magnitude full precision; ties -> positive first, then smallest k
// == reference first-occurrence argmax over [d0..d8, -d0..-d8].
// ---------------------------------------------------------------------------
__global__ __launch_bounds__(256, 4) void hog_gather(const float* __restrict__ img) {
    __shared__ unsigned int s_pack[WROWS * MP];   // 18496 B
    __shared__ float        s_bins[18 * 256];     // 18432 B  (total 36928 B)

    const int tid = threadIdx.x;
    const int cx0 = blockIdx.x * TS;
    const int cy0 = blockIdx.y * TS;
    const int b   = blockIdx.z;

    const int y0  = 4 * cy0 - 2;        // image row of window row 0
    const int x0a = 4 * cx0 - 4;        // aligned image col of strip 0

    const float* base = img + (size_t)b * NCH * IH * IW;

    const float UU[9] = {1.0f, 0.9397f, 0.766f, 0.5f, 0.1736f,
                         -0.1736f, -0.5f, -0.766f, -0.9397f};
    const float VV[9] = {0.0f, 0.342f, 0.6428f, 0.866f, 0.9848f,
                         0.9848f, 0.866f, 0.6428f, 0.342f};

    // ---- zero per-thread bins (owner-only; sync below covers it) ----
#pragma unroll
    for (int o = 0; o < 18; o++) s_bins[o * 256 + tid] = 0.0f;

    // ---- Stage 1: per-pixel gradient / orientation, 4-px aligned strips ----
    for (int t = tid; t < NSTRIP * WROWS; t += 256) {
        const int s  = t % NSTRIP;
        const int py = t / NSTRIP;
        const int y  = y0 + py;
        const int xb = x0a + 4 * s;

        unsigned int pk[4] = {0u, 0u, 0u, 0u};

        if (y >= 1 && y <= IH - 2 && xb >= 0 && xb <= IW - 4) {
            float bestv[4] = {-1.f, -1.f, -1.f, -1.f};
            float bdx[4], bdy[4];
#pragma unroll
            for (int c = 0; c < NCH; c++) {
                const float* rp = base + (size_t)c * IH * IW + (size_t)y * IW + xb;
                float4 up = *reinterpret_cast<const float4*>(rp - IW);
                float4 dn = *reinterpret_cast<const float4*>(rp + IW);
                float4 md = *reinterpret_cast<const float4*>(rp);
                float  lf = (xb >= 1) ? rp[-1] : 0.f;
                float  rt = (xb + 4 <= IW - 1) ? rp[4] : 0.f;
                float mx[6] = {lf, md.x, md.y, md.z, md.w, rt};
                float u[4]  = {up.x, up.y, up.z, up.w};
                float d[4]  = {dn.x, dn.y, dn.z, dn.w};
#pragma unroll
                for (int i = 0; i < 4; i++) {
                    float gdy = d[i] - u[i];
                    float gdx = mx[i + 2] - mx[i];
                    float v = gdx * gdx + gdy * gdy;
                    if (v > bestv[i]) { bestv[i] = v; bdx[i] = gdx; bdy[i] = gdy; }
                }
            }
#pragma unroll
            for (int i = 0; i < 4; i++) {
                const float gdx = bdx[i];
                const float gdy = bdy[i];

                unsigned long long best = 0ull;
#pragma unroll
                for (int k = 0; k < 9; k++) {
                    float dd = UU[k] * gdx + VV[k] * gdy;
                    unsigned int xbits = __float_as_uint(dd);
                    unsigned int lo = ((~xbits >> 26) & 32u) | (unsigned)(31 - k);
                    unsigned long long p =
                        ((unsigned long long)(xbits & 0x7FFFFFFFu) << 6) | lo;
                    best = (p > best) ? p : best;
                }
                int kk = 31 - (int)(best & 31u);
                int bo = (best & 32u) ? kk : kk + 9;

                float vm = bestv[i];
                float mag = (vm > 0.f) ? vm * rsqrtf(vm) : 0.f;
                int x = xb + i;
                if (x < 1 || x > IW - 2) mag = 0.f;
                pk[i] = (__float_as_uint(mag) & 0xFFFFFFE0u) | (unsigned)bo;
            }
        }
#pragma unroll
        for (int i = 0; i < 4; i++) {
            int sc = 4 * s - 2 + i;
            if (sc >= 0 && sc < WCOLS) s_pack[py * MP + sc] = pk[i];
        }
    }

    __syncthreads();

    // ---- Stage 3: gather 8x8 pixel footprint per cell (1 thread = 1 cell) ----
    const int lcy = tid >> 4;
    const int lcx = tid & 15;
    const int pr  = 4 * lcy;
    const int pc  = 4 * lcx;

    const float W8[8] = {0.125f, 0.375f, 0.625f, 0.875f,
                         0.875f, 0.625f, 0.375f, 0.125f};

#pragma unroll
    for (int dy = 0; dy < 8; dy++) {
        const float wy = W8[dy];
        const unsigned int* rowp = &s_pack[(pr + dy) * MP + pc];
        uint4 p0 = *reinterpret_cast<const uint4*>(rowp);
        uint4 p1 = *reinterpret_cast<const uint4*>(rowp + 4);
        unsigned int uu[8] = {p0.x, p0.y, p0.z, p0.w, p1.x, p1.y, p1.z, p1.w};
#pragma unroll
        for (int dx = 0; dx < 8; dx++) {
            unsigned int u = uu[dx];
            float m = __uint_as_float(u & 0xFFFFFFE0u);
            int o = (int)(u & 31u);
            s_bins[o * 256 + tid] += m * (wy * W8[dx]);
        }
    }

    // ---- Stage 4: write hist + norm (coalesced stores) ----
    const int cy = cy0 + lcy;
    const int cx = cx0 + lcx;
    float* hb = g_hist + ((size_t)b * 18) * (BH * BW) + cy * BW + cx;

    float acc = 0.0f;
#pragma unroll
    for (int o = 0; o < 9; o++) {
        float a = s_bins[o * 256 + tid];
        float c = s_bins[(o + 9) * 256 + tid];
        hb[o * (BH * BW)]       = a;
        hb[(o + 9) * (BH * BW)] = c;
        float s = a + c;
        acc += s * s;
    }
    g_norm[(size_t)b * BH * BW + cy * BW + cx] = acc;
}

// ---------------------------------------------------------------------------
// Kernel 2: block-normalized features (31 channels), 1 px/thread.
// Single fused loop: each hist plane pair (o, o+9) loaded once, channels
// o, o+9, 18+o written immediately — no persistent src[18] array.
// ---------------------------------------------------------------------------
__global__ __launch_bounds__(256) void hog_feat(float* __restrict__ out) {
    int idx = blockIdx.x * blockDim.x + threadIdx.x;
    if (idx >= BATCH * BH * BW) return;
    int j = idx & (BW - 1);
    int t = idx >> 7;
    int i = t & (BH - 1);
    int b = t >> 7;

    float* ob = out + (size_t)b * 31 * BH * BW + i * BW + j;

    if (i == 0 || i == BH - 1 || j == 0 || j == BW - 1) {
#pragma unroll
        for (int ch = 0; ch < 31; ch++) ob[ch * (BH * BW)] = 0.0f;
        return;
    }

    const float* nb = g_norm + (size_t)b * BH * BW;
    const float EPS = 0.0001f;
#define NRM(a, c) nb[(a) * BW + (c)]
    float n1 = rsqrtf(NRM(i, j) + NRM(i + 1, j) + NRM(i, j + 1) + NRM(i + 1, j + 1) + EPS);
    float n2 = rsqrtf(NRM(i - 1, j) + NRM(i, j) + NRM(i - 1, j + 1) + NRM(i, j + 1) + EPS);
    float n3 = rsqrtf(NRM(i, j - 1) + NRM(i + 1, j - 1) + NRM(i, j) + NRM(i + 1, j) + EPS);
    float n4 = rsqrtf(NRM(i - 1, j - 1) + NRM(i, j - 1) + NRM(i - 1, j) + NRM(i, j) + EPS);
#undef NRM

    const float* hb = g_hist + (size_t)b * 18 * BH * BW + i * BW + j;

    float t1 = 0.f, t2 = 0.f, t3 = 0.f, t4 = 0.f;
#pragma unroll
    for (int o = 0; o < 9; o++) {
        float a = hb[o * (BH * BW)];
        float c = hb[(o + 9) * (BH * BW)];

        float a1 = fminf(a * n1, 0.2f);
        float a2 = fminf(a * n2, 0.2f);
        float a3 = fminf(a * n3, 0.2f);
        float a4 = fminf(a * n4, 0.2f);
        float c1 = fminf(c * n1, 0.2f);
        float c2 = fminf(c * n2, 0.2f);
        float c3 = fminf(c * n3, 0.2f);
        float c4 = fminf(c * n4, 0.2f);

        ob[o * (BH * BW)]       = 0.5f * (a1 + a2 + a3 + a4);
        ob[(o + 9) * (BH * BW)] = 0.5f * (c1 + c2 + c3 + c4);

        float ss = a + c;
        float v = fminf(ss * n1, 0.2f) + fminf(ss * n2, 0.2f) +
                  fminf(ss * n3, 0.2f) + fminf(ss * n4, 0.2f);
        ob[(18 + o) * (BH * BW)] = 0.5f * v;

        t1 += a1 + c1;
        t2 += a2 + c2;
        t3 += a3 + c3;
        t4 += a4 + c4;
    }
    ob[27 * (BH * BW)] = 0.2357f * t1;
    ob[28 * (BH * BW)] = 0.2357f * t2;
    ob[29 * (BH * BW)] = 0.2357f * t3;
    ob[30 * (BH * BW)] = 0.2357f * t4;
}

// ---------------------------------------------------------------------------
extern "C" void kernel_launch(void* const* d_in, const int* in_sizes, int n_in,
                              void* d_out, int out_size) {
    const float* img = (const float*)d_in[0];
    float* out = (float*)d_out;

    dim3 grid(BW / TS, BH / TS, BATCH);   // (8, 8, 16)
    hog_gather<<<grid, 256>>>(img);

    int n = BATCH * BH * BW;
    hog_feat<<<(n + 255) / 256, 256>>>(out);
}

// round 9
// speedup vs baseline: 1.2800x; 1.2800x over previous
#include <cuda_runtime.h>
#include <math.h>
#include <float.h>

// Fixed problem shape: img (16,3,512,512) f32, sbin=4 -> out (16,31,128,128) f32
#define BATCH 16
#define NCH   3
#define IH    512
#define IW    512
#define BH    128
#define BW    128

#define TS     16         // cells per tile side
#define WROWS  68         // pixel rows in window
#define WCOLS  68         // pixel cols in window
#define MP     68         // smem pitch (u32), multiple of 4 for LDS.128
#define NSTRIP 18         // 4-px strips per row (covers sc -2..69)

#define HIST_ELEMS (BATCH * 18 * BH * BW)
#define NORM_ELEMS (BATCH * BH * BW)

__device__ float g_hist[HIST_ELEMS];
__device__ float g_norm[NORM_ELEMS];

// ---------------------------------------------------------------------------
// Kernel 1: gradients + orientation + per-cell gather + norm.
// One block = 16x16 cells. mag|bo packed in one u32 (bo in 5 low mantissa bits).
// Orientation argmax (EXACT, cheap): fmax/fmin trees + equality mask + ffs.
// ---------------------------------------------------------------------------
__global__ __launch_bounds__(256, 3) void hog_gather(const float* __restrict__ img) {
    __shared__ unsigned int s_pack[WROWS * MP];   // 18496 B
    __shared__ float        s_bins[18 * 256];     // 18432 B  (total 36928 B)

    const int tid = threadIdx.x;
    const int cx0 = blockIdx.x * TS;
    const int cy0 = blockIdx.y * TS;
    const int b   = blockIdx.z;

    const int y0  = 4 * cy0 - 2;        // image row of window row 0
    const int x0a = 4 * cx0 - 4;        // aligned image col of strip 0

    const float* base = img + (size_t)b * NCH * IH * IW;

    const float UU[9] = {1.0f, 0.9397f, 0.766f, 0.5f, 0.1736f,
                         -0.1736f, -0.5f, -0.766f, -0.9397f};
    const float VV[9] = {0.0f, 0.342f, 0.6428f, 0.866f, 0.9848f,
                         0.9848f, 0.866f, 0.6428f, 0.342f};

    // ---- zero per-thread bins (owner-only; sync below covers it) ----
#pragma unroll
    for (int o = 0; o < 18; o++) s_bins[o * 256 + tid] = 0.0f;

    // ---- Stage 1: per-pixel gradient / orientation, 4-px aligned strips ----
    for (int t = tid; t < NSTRIP * WROWS; t += 256) {
        const int s  = t % NSTRIP;
        const int py = t / NSTRIP;
        const int y  = y0 + py;
        const int xb = x0a + 4 * s;

        unsigned int pk[4] = {0u, 0u, 0u, 0u};

        if (y >= 1 && y <= IH - 2 && xb >= 0 && xb <= IW - 4) {
            float bestv[4] = {-1.f, -1.f, -1.f, -1.f};
            float bdx[4], bdy[4];
#pragma unroll
            for (int c = 0; c < NCH; c++) {
                const float* rp = base + (size_t)c * IH * IW + (size_t)y * IW + xb;
                float4 up = *reinterpret_cast<const float4*>(rp - IW);
                float4 dn = *reinterpret_cast<const float4*>(rp + IW);
                float4 md = *reinterpret_cast<const float4*>(rp);
                float  lf = (xb >= 1) ? rp[-1] : 0.f;
                float  rt = (xb + 4 <= IW - 1) ? rp[4] : 0.f;
                float mx[6] = {lf, md.x, md.y, md.z, md.w, rt};
                float u[4]  = {up.x, up.y, up.z, up.w};
                float d[4]  = {dn.x, dn.y, dn.z, dn.w};
#pragma unroll
                for (int i = 0; i < 4; i++) {
                    float gdy = d[i] - u[i];
                    float gdx = mx[i + 2] - mx[i];
                    float v = gdx * gdx + gdy * gdy;
                    if (v > bestv[i]) { bestv[i] = v; bdx[i] = gdx; bdy[i] = gdy; }
                }
            }
#pragma unroll
            for (int i = 0; i < 4; i++) {
                const float gdx = bdx[i];
                const float gdy = bdy[i];

                float d[9];
#pragma unroll
                for (int k = 0; k < 9; k++) d[k] = UU[k] * gdx + VV[k] * gdy;

                // parallel max/min trees (FMNMX, exact)
                float mx01 = fmaxf(d[0], d[1]), mx23 = fmaxf(d[2], d[3]);
                float mx45 = fmaxf(d[4], d[5]), mx67 = fmaxf(d[6], d[7]);
                float mxv = fmaxf(fmaxf(fmaxf(mx01, mx23), fmaxf(mx45, mx67)), d[8]);
                float mn01 = fminf(d[0], d[1]), mn23 = fminf(d[2], d[3]);
                float mn45 = fminf(d[4], d[5]), mn67 = fminf(d[6], d[7]);
                float mnv = fminf(fminf(fminf(mn01, mn23), fminf(mn45, mn67)), d[8]);

                // positives (indices 0-8) come first in the reference concat:
                // on exact tie, positive side wins -> >=
                bool pos = (mxv >= -mnv);
                float tgt = pos ? mxv : mnv;

                unsigned int mask = 0u;
#pragma unroll
                for (int k = 0; k < 9; k++)
                    mask |= (d[k] == tgt) ? (1u << k) : 0u;
                int kk = __ffs(mask) - 1;          // first occurrence
                int bo = pos ? kk : kk + 9;

                float vm = bestv[i];
                float mag = (vm > 0.f) ? vm * rsqrtf(vm) : 0.f;
                int x = xb + i;
                if (x < 1 || x > IW - 2) mag = 0.f;
                pk[i] = (__float_as_uint(mag) & 0xFFFFFFE0u) | (unsigned)bo;
            }
        }
#pragma unroll
        for (int i = 0; i < 4; i++) {
            int sc = 4 * s - 2 + i;
            if (sc >= 0 && sc < WCOLS) s_pack[py * MP + sc] = pk[i];
        }
    }

    __syncthreads();

    // ---- Stage 3: gather 8x8 pixel footprint per cell (1 thread = 1 cell) ----
    const int lcy = tid >> 4;
    const int lcx = tid & 15;
    const int pr  = 4 * lcy;
    const int pc  = 4 * lcx;

    const float W8[8] = {0.125f, 0.375f, 0.625f, 0.875f,
                         0.875f, 0.625f, 0.375f, 0.125f};

#pragma unroll
    for (int dy = 0; dy < 8; dy++) {
        const float wy = W8[dy];
        const unsigned int* rowp = &s_pack[(pr + dy) * MP + pc];
        uint4 p0 = *reinterpret_cast<const uint4*>(rowp);
        uint4 p1 = *reinterpret_cast<const uint4*>(rowp + 4);
        unsigned int uu[8] = {p0.x, p0.y, p0.z, p0.w, p1.x, p1.y, p1.z, p1.w};
#pragma unroll
        for (int dx = 0; dx < 8; dx++) {
            unsigned int u = uu[dx];
            float m = __uint_as_float(u & 0xFFFFFFE0u);
            int o = (int)(u & 31u);
            s_bins[o * 256 + tid] += m * (wy * W8[dx]);
        }
    }

    // ---- Stage 4: write hist + norm (coalesced stores) ----
    const int cy = cy0 + lcy;
    const int cx = cx0 + lcx;
    float* hb = g_hist + ((size_t)b * 18) * (BH * BW) + cy * BW + cx;

    float acc = 0.0f;
#pragma unroll
    for (int o = 0; o < 9; o++) {
        float a = s_bins[o * 256 + tid];
        float c = s_bins[(o + 9) * 256 + tid];
        hb[o * (BH * BW)]       = a;
        hb[(o + 9) * (BH * BW)] = c;
        float s = a + c;
        acc += s * s;
    }
    g_norm[(size_t)b * BH * BW + cy * BW + cx] = acc;
}

// ---------------------------------------------------------------------------
// Kernel 2: block-normalized features, 4 px/thread, float4 I/O, fused o-loop.
// ---------------------------------------------------------------------------
__global__ __launch_bounds__(128) void hog_feat(float* __restrict__ out) {
    const int idx = blockIdx.x * 128 + threadIdx.x;   // 65536 total
    const int g = idx & 31;            // j = 4*g
    const int i = (idx >> 5) & 127;
    const int b = idx >> 12;
    const int j = g * 4;

    float* ob = out + (size_t)b * 31 * BH * BW + i * BW + j;

    if (i == 0 || i == BH - 1) {
        const float4 z = make_float4(0.f, 0.f, 0.f, 0.f);
#pragma unroll
        for (int ch = 0; ch < 31; ch++)
            *reinterpret_cast<float4*>(&ob[ch * (BH * BW)]) = z;
        return;
    }

    // column masks (exact zero for border elements)
    const float mk0 = (g == 0)  ? 0.f : 1.f;
    const float mk3 = (g == 31) ? 0.f : 1.f;
    const float mk[4] = {mk0, 1.f, 1.f, mk3};

    // norm neighborhood: rows i-1..i+1, cols j-1..j+4 (6 values per row)
    const float* nb = g_norm + (size_t)b * BH * BW;
    float arr[3][6];
#pragma unroll
    for (int r = 0; r < 3; r++) {
        const float* p = nb + (i - 1 + r) * BW;
        float4 v = *reinterpret_cast<const float4*>(&p[j]);
        arr[r][1] = v.x; arr[r][2] = v.y; arr[r][3] = v.z; arr[r][4] = v.w;
        arr[r][0] = (g > 0)  ? p[j - 1] : 0.f;   // unused when masked
        arr[r][5] = (g < 31) ? p[j + 4] : 0.f;   // unused when masked
    }

    const float EPS = 0.0001f;
    float n1[4], n2[4], n3[4], n4[4];
#pragma unroll
    for (int e = 0; e < 4; e++) {
        n1[e] = rsqrtf(arr[1][e + 1] + arr[2][e + 1] + arr[1][e + 2] + arr[2][e + 2] + EPS);
        n2[e] = rsqrtf(arr[0][e + 1] + arr[1][e + 1] + arr[0][e + 2] + arr[1][e + 2] + EPS);
        n3[e] = rsqrtf(arr[1][e] + arr[2][e] + arr[1][e + 1] + arr[2][e + 1] + EPS);
        n4[e] = rsqrtf(arr[0][e] + arr[1][e] + arr[0][e + 1] + arr[1][e + 1] + EPS);
    }

    const float* hb = g_hist + (size_t)b * 18 * BH * BW + i * BW + j;

    float t1[4] = {0.f, 0.f, 0.f, 0.f};
    float t2[4] = {0.f, 0.f, 0.f, 0.f};
    float t3[4] = {0.f, 0.f, 0.f, 0.f};
    float t4[4] = {0.f, 0.f, 0.f, 0.f};

#pragma unroll
    for (int o = 0; o < 9; o++) {
        float4 a4 = *reinterpret_cast<const float4*>(&hb[o * (BH * BW)]);
        float4 c4 = *reinterpret_cast<const float4*>(&hb[(o + 9) * (BH * BW)]);
        float a[4] = {a4.x, a4.y, a4.z, a4.w};
        float c[4] = {c4.x, c4.y, c4.z, c4.w};

        float ra[4], rc[4], ri[4];
#pragma unroll
        for (int e = 0; e < 4; e++) {
            float a1 = fminf(a[e] * n1[e], 0.2f);
            float a2 = fminf(a[e] * n2[e], 0.2f);
            float a3 = fminf(a[e] * n3[e], 0.2f);
            float a4s = fminf(a[e] * n4[e], 0.2f);
            float c1 = fminf(c[e] * n1[e], 0.2f);
            float c2 = fminf(c[e] * n2[e], 0.2f);
            float c3 = fminf(c[e] * n3[e], 0.2f);
            float c4s = fminf(c[e] * n4[e], 0.2f);

            ra[e] = mk[e] * 0.5f * (a1 + a2 + a3 + a4s);
            rc[e] = mk[e] * 0.5f * (c1 + c2 + c3 + c4s);

            float ss = a[e] + c[e];
            float v = fminf(ss * n1[e], 0.2f) + fminf(ss * n2[e], 0.2f) +
                      fminf(ss * n3[e], 0.2f) + fminf(ss * n4[e], 0.2f);
            ri[e] = mk[e] * 0.5f * v;

            t1[e] += a1 + c1;
            t2[e] += a2 + c2;
            t3[e] += a3 + c3;
            t4[e] += a4s + c4s;
        }
        *reinterpret_cast<float4*>(&ob[o * (BH * BW)])        = make_float4(ra[0], ra[1], ra[2], ra[3]);
        *reinterpret_cast<float4*>(&ob[(o + 9) * (BH * BW)])  = make_float4(rc[0], rc[1], rc[2], rc[3]);
        *reinterpret_cast<float4*>(&ob[(18 + o) * (BH * BW)]) = make_float4(ri[0], ri[1], ri[2], ri[3]);
    }

    *reinterpret_cast<float4*>(&ob[27 * (BH * BW)]) =
        make_float4(mk[0] * 0.2357f * t1[0], mk[1] * 0.2357f * t1[1],
                    mk[2] * 0.2357f * t1[2], mk[3] * 0.2357f * t1[3]);
    *reinterpret_cast<float4*>(&ob[28 * (BH * BW)]) =
        make_float4(mk[0] * 0.2357f * t2[0], mk[1] * 0.2357f * t2[1],
                    mk[2] * 0.2357f * t2[2], mk[3] * 0.2357f * t2[3]);
    *reinterpret_cast<float4*>(&ob[29 * (BH * BW)]) =
        make_float4(mk[0] * 0.2357f * t3[0], mk[1] * 0.2357f * t3[1],
                    mk[2] * 0.2357f * t3[2], mk[3] * 0.2357f * t3[3]);
    *reinterpret_cast<float4*>(&ob[30 * (BH * BW)]) =
        make_float4(mk[0] * 0.2357f * t4[0], mk[1] * 0.2357f * t4[1],
                    mk[2] * 0.2357f * t4[2], mk[3] * 0.2357f * t4[3]);
}

// ---------------------------------------------------------------------------
extern "C" void kernel_launch(void* const* d_in, const int* in_sizes, int n_in,
                              void* d_out, int out_size) {
    const float* img = (const float*)d_in[0];
    float* out = (float*)d_out;

    dim3 grid(BW / TS, BH / TS, BATCH);   // (8, 8, 16)
    hog_gather<<<grid, 256>>>(img);

    hog_feat<<<512, 128>>>(out);          // 65536 threads, 4 px each
}

// round 10
// speedup vs baseline: 1.2809x; 1.0007x over previous
#include <cuda_runtime.h>
#include <math.h>
#include <float.h>

// Fixed problem shape: img (16,3,512,512) f32, sbin=4 -> out (16,31,128,128) f32
#define BATCH 16
#define NCH   3
#define IH    512
#define IW    512
#define BH    128
#define BW    128

#define TS     16         // cells per tile side
#define WROWS  68         // pixel rows in window
#define MP     72         // smem pitch (u32): si = 0..71, 16B-aligned strip stores
#define NSTRIP 18         // 4-px strips per row

#define HIST_ELEMS (BATCH * 18 * BH * BW)
#define NORM_ELEMS (BATCH * BH * BW)

__device__ float g_hist[HIST_ELEMS];
__device__ float g_norm[NORM_ELEMS];

// ---------------------------------------------------------------------------
// Kernel 1: gradients + orientation + per-cell gather + norm.
// One block = 16x16 cells. mag|bo packed in one u32 (bo in 5 low mantissa bits).
// Stage-1 strip stores are UNGUARDED aligned STS.128 (window shifted by +2).
// ---------------------------------------------------------------------------
__global__ __launch_bounds__(256, 3) void hog_gather(const float* __restrict__ img) {
    __shared__ unsigned int s_pack[WROWS * MP];   // 19584 B
    __shared__ float        s_bins[18 * 256];     // 18432 B  (total 38016 B)

    const int tid = threadIdx.x;
    const int cx0 = blockIdx.x * TS;
    const int cy0 = blockIdx.y * TS;
    const int b   = blockIdx.z;

    const int y0  = 4 * cy0 - 2;        // image row of window row 0
    const int x0a = 4 * cx0 - 4;        // image col of smem col 0 (aligned)

    const float* base = img + (size_t)b * NCH * IH * IW;

    const float UU[9] = {1.0f, 0.9397f, 0.766f, 0.5f, 0.1736f,
                         -0.1736f, -0.5f, -0.766f, -0.9397f};
    const float VV[9] = {0.0f, 0.342f, 0.6428f, 0.866f, 0.9848f,
                         0.9848f, 0.866f, 0.6428f, 0.342f};

    // ---- zero per-thread bins (owner-only; sync below covers it) ----
#pragma unroll
    for (int o = 0; o < 18; o++) s_bins[o * 256 + tid] = 0.0f;

    // ---- Stage 1: per-pixel gradient / orientation, 4-px aligned strips ----
    for (int t = tid; t < NSTRIP * WROWS; t += 256) {
        const int s  = t % NSTRIP;
        const int py = t / NSTRIP;
        const int y  = y0 + py;
        const int xb = x0a + 4 * s;

        uint4 pk = make_uint4(0u, 0u, 0u, 0u);

        if (y >= 1 && y <= IH - 2 && xb >= 0 && xb <= IW - 4) {
            float bestv[4] = {-1.f, -1.f, -1.f, -1.f};
            float bdx[4], bdy[4];
#pragma unroll
            for (int c = 0; c < NCH; c++) {
                const float* rp = base + (size_t)c * IH * IW + (size_t)y * IW + xb;
                float4 up = *reinterpret_cast<const float4*>(rp - IW);
                float4 dn = *reinterpret_cast<const float4*>(rp + IW);
                float4 md = *reinterpret_cast<const float4*>(rp);
                float  lf = (xb > 0) ? rp[-1] : 0.f;
                float  rt = (xb + 4 <= IW - 1) ? rp[4] : 0.f;
                float mx[6] = {lf, md.x, md.y, md.z, md.w, rt};
                float u[4]  = {up.x, up.y, up.z, up.w};
                float d[4]  = {dn.x, dn.y, dn.z, dn.w};
#pragma unroll
                for (int i = 0; i < 4; i++) {
                    float gdy = d[i] - u[i];
                    float gdx = mx[i + 2] - mx[i];
                    float v = gdx * gdx + gdy * gdy;
                    if (v > bestv[i]) { bestv[i] = v; bdx[i] = gdx; bdy[i] = gdy; }
                }
            }
            unsigned int pka[4];
#pragma unroll
            for (int i = 0; i < 4; i++) {
                const float gdx = bdx[i];
                const float gdy = bdy[i];

                float d[9];
#pragma unroll
                for (int k = 0; k < 9; k++) d[k] = UU[k] * gdx + VV[k] * gdy;

                // parallel max/min trees (FMNMX, exact)
                float mx01 = fmaxf(d[0], d[1]), mx23 = fmaxf(d[2], d[3]);
                float mx45 = fmaxf(d[4], d[5]), mx67 = fmaxf(d[6], d[7]);
                float mxv = fmaxf(fmaxf(fmaxf(mx01, mx23), fmaxf(mx45, mx67)), d[8]);
                float mn01 = fminf(d[0], d[1]), mn23 = fminf(d[2], d[3]);
                float mn45 = fminf(d[4], d[5]), mn67 = fminf(d[6], d[7]);
                float mnv = fminf(fminf(fminf(mn01, mn23), fminf(mn45, mn67)), d[8]);

                // positives first on exact tie -> >=
                bool pos = (mxv >= -mnv);
                float tgt = pos ? mxv : mnv;

                unsigned int mask = 0u;
#pragma unroll
                for (int k = 0; k < 9; k++)
                    mask |= (d[k] == tgt) ? (1u << k) : 0u;
                int kk = __ffs(mask) - 1;          // first occurrence
                int bo = pos ? kk : kk + 9;

                float vm = bestv[i];
                float mag = (vm > 0.f) ? vm * rsqrtf(vm) : 0.f;
                int x = xb + i;
                if (x < 1 || x > IW - 2) mag = 0.f;
                pka[i] = (__float_as_uint(mag) & 0xFFFFFFE0u) | (unsigned)bo;
            }
            pk = make_uint4(pka[0], pka[1], pka[2], pka[3]);
        }
        // unguarded aligned 16B store: si = 4s .. 4s+3
        *reinterpret_cast<uint4*>(&s_pack[py * MP + 4 * s]) = pk;
    }

    __syncthreads();

    // ---- Stage 3: gather 8x8 pixel footprint per cell (1 thread = 1 cell) ----
    // pixel x = 4*cell_x - 2 + dx  ->  si = 4*lcx + 2 + dx  (elements [2..9])
    const int lcy = tid >> 4;
    const int lcx = tid & 15;
    const int pr  = 4 * lcy;
    const int pc  = 4 * lcx;

    const float W8[8] = {0.125f, 0.375f, 0.625f, 0.875f,
                         0.875f, 0.625f, 0.375f, 0.125f};

#pragma unroll
    for (int dy = 0; dy < 8; dy++) {
        const float wy = W8[dy];
        const unsigned int* rowp = &s_pack[(pr + dy) * MP + pc];
        uint4 p0 = *reinterpret_cast<const uint4*>(rowp);
        uint4 p1 = *reinterpret_cast<const uint4*>(rowp + 4);
        uint4 p2 = *reinterpret_cast<const uint4*>(rowp + 8);
        unsigned int v[12] = {p0.x, p0.y, p0.z, p0.w,
                              p1.x, p1.y, p1.z, p1.w,
                              p2.x, p2.y, p2.z, p2.w};
#pragma unroll
        for (int dx = 0; dx < 8; dx++) {
            unsigned int u = v[dx + 2];
            float m = __uint_as_float(u & 0xFFFFFFE0u);
            int o = (int)(u & 31u);
            s_bins[o * 256 + tid] += m * (wy * W8[dx]);
        }
    }

    // ---- Stage 4: write hist + norm (coalesced stores) ----
    const int cy = cy0 + lcy;
    const int cx = cx0 + lcx;
    float* hb = g_hist + ((size_t)b * 18) * (BH * BW) + cy * BW + cx;

    float acc = 0.0f;
#pragma unroll
    for (int o = 0; o < 9; o++) {
        float a = s_bins[o * 256 + tid];
        float c = s_bins[(o + 9) * 256 + tid];
        hb[o * (BH * BW)]       = a;
        hb[(o + 9) * (BH * BW)] = c;
        float s = a + c;
        acc += s * s;
    }
    g_norm[(size_t)b * BH * BW + cy * BW + cx] = acc;
}

// ---------------------------------------------------------------------------
// Kernel 2: block-normalized features, 1 px/thread.
// ALL 27 loads front-batched (MLP) before any dependent compute, then the
// fused o-loop (each plane pair -> channels o, o+9, 18+o).
// ---------------------------------------------------------------------------
__global__ __launch_bounds__(256) void hog_feat(float* __restrict__ out) {
    int idx = blockIdx.x * blockDim.x + threadIdx.x;
    if (idx >= BATCH * BH * BW) return;
    int j = idx & (BW - 1);
    int t = idx >> 7;
    int i = t & (BH - 1);
    int b = t >> 7;

    float* ob = out + (size_t)b * 31 * BH * BW + i * BW + j;

    if (i == 0 || i == BH - 1 || j == 0 || j == BW - 1) {
#pragma unroll
        for (int ch = 0; ch < 31; ch++) ob[ch * (BH * BW)] = 0.0f;
        return;
    }

    // ---- front-batched loads: 18 hist + 9 norm ----
    const float* hb = g_hist + (size_t)b * 18 * BH * BW + i * BW + j;
    float src[18];
#pragma unroll
    for (int o = 0; o < 18; o++) src[o] = hb[o * (BH * BW)];

    const float* nb = g_norm + (size_t)b * BH * BW;
    float m[3][3];
#pragma unroll
    for (int r = 0; r < 3; r++)
#pragma unroll
        for (int c = 0; c < 3; c++)
            m[r][c] = nb[(i - 1 + r) * BW + (j - 1 + c)];

    const float EPS = 0.0001f;
    float n1 = rsqrtf(m[1][1] + m[2][1] + m[1][2] + m[2][2] + EPS);
    float n2 = rsqrtf(m[0][1] + m[1][1] + m[0][2] + m[1][2] + EPS);
    float n3 = rsqrtf(m[1][0] + m[2][0] + m[1][1] + m[2][1] + EPS);
    float n4 = rsqrtf(m[0][0] + m[1][0] + m[0][1] + m[1][1] + EPS);

    float t1 = 0.f, t2 = 0.f, t3 = 0.f, t4 = 0.f;
#pragma unroll
    for (int o = 0; o < 9; o++) {
        float a = src[o];
        float c = src[o + 9];

        float a1 = fminf(a * n1, 0.2f);
        float a2 = fminf(a * n2, 0.2f);
        float a3 = fminf(a * n3, 0.2f);
        float a4 = fminf(a * n4, 0.2f);
        float c1 = fminf(c * n1, 0.2f);
        float c2 = fminf(c * n2, 0.2f);
        float c3 = fminf(c * n3, 0.2f);
        float c4 = fminf(c * n4, 0.2f);

        ob[o * (BH * BW)]       = 0.5f * (a1 + a2 + a3 + a4);
        ob[(o + 9) * (BH * BW)] = 0.5f * (c1 + c2 + c3 + c4);

        float ss = a + c;
        float v = fminf(ss * n1, 0.2f) + fminf(ss * n2, 0.2f) +
                  fminf(ss * n3, 0.2f) + fminf(ss * n4, 0.2f);
        ob[(18 + o) * (BH * BW)] = 0.5f * v;

        t1 += a1 + c1;
        t2 += a2 + c2;
        t3 += a3 + c3;
        t4 += a4 + c4;
    }
    ob[27 * (BH * BW)] = 0.2357f * t1;
    ob[28 * (BH * BW)] = 0.2357f * t2;
    ob[29 * (BH * BW)] = 0.2357f * t3;
    ob[30 * (BH * BW)] = 0.2357f * t4;
}

// ---------------------------------------------------------------------------
extern "C" void kernel_launch(void* const* d_in, const int* in_sizes, int n_in,
                              void* d_out, int out_size) {
    const float* img = (const float*)d_in[0];
    float* out = (float*)d_out;

    dim3 grid(BW / TS, BH / TS, BATCH);   // (8, 8, 16)
    hog_gather<<<grid, 256>>>(img);

    int n = BATCH * BH * BW;
    hog_feat<<<(n + 255) / 256, 256>>>(out);
}